// round 3
// baseline (speedup 1.0000x reference)
#include <cuda_runtime.h>
#include <cstdint>

#define NF 9
#define HD 128
#define VOCAB 128
#define GMAX 1024
#define OUTD 10
#define MAXN 100000
#define BN_EPS 1e-5f

// ---------------- scratch (device globals; no allocs allowed) ----------------
__device__ float g_h[(size_t)MAXN * HD];
__device__ float g_hw[(size_t)MAXN * HD];
__device__ float g_acc[(size_t)MAXN * HD];
__device__ float g_deg[MAXN];
__device__ float g_dinv[MAXN];
__device__ float g_pool[GMAX * HD];
__device__ float g_cnt[GMAX];

// 128-bit vector reduction: 4 f32 adds in one L2 atomic op
__device__ __forceinline__ void red4(float* p, float4 v) {
    asm volatile("red.global.add.v4.f32 [%0], {%1,%2,%3,%4};"
                 :: "l"(p), "f"(v.x), "f"(v.y), "f"(v.z), "f"(v.w) : "memory");
}

// ---------------- degree / dinv ----------------
__global__ void deg_init_k(int N) {
    int n = blockIdx.x * blockDim.x + threadIdx.x;
    if (n < N) g_deg[n] = 1.0f;   // self-loop
}
__global__ void deg_count_k(const int* __restrict__ dst, int E) {
    int e = blockIdx.x * blockDim.x + threadIdx.x;
    if (e < E) atomicAdd(&g_deg[dst[e]], 1.0f);
}
__global__ void dinv_k(int N) {
    int n = blockIdx.x * blockDim.x + threadIdx.x;
    if (n < N) g_dinv[n] = rsqrtf(g_deg[n]);
}

// ---------------- AtomEncoder: h[n][c] = sum_f emb[f][x[n][f]][c] ----------------
__global__ void embed_k(const int* __restrict__ x, const float* __restrict__ emb, int N) {
    int n = blockIdx.x;
    int c = threadIdx.x;
    const int* xr = x + (size_t)n * NF;
    float s = 0.0f;
#pragma unroll
    for (int f = 0; f < NF; f++) {
        int id = __ldg(xr + f);
        s += __ldg(emb + ((size_t)f * VOCAB + id) * HD + c);
    }
    g_h[(size_t)n * HD + c] = s;
}

// ---------------- GEMM: hw_s = (g_h @ W) * dinv[row]; also zeroes g_acc ----------------
#define HS 132   // padded hsh row stride
__global__ __launch_bounds__(256) void gemm_k(const float* __restrict__ W, int N) {
    extern __shared__ float smem[];
    float* Wsh = smem;                 // 128*128
    float* hsh = smem + HD * HD;       // 64*HS
    const int tid = threadIdx.x;
    const int row0 = blockIdx.x * 64;

    // load W (128x128 = 4096 float4)
#pragma unroll
    for (int i = 0; i < 16; i++) {
        int idx = tid + i * 256;
        ((float4*)Wsh)[idx] = __ldg((const float4*)W + idx);
    }
    // load h tile (64x128 -> padded stride)
#pragma unroll
    for (int i = 0; i < 8; i++) {
        int slot = tid + i * 256;          // float4 slot over 64x32
        int r = slot >> 5, k4 = slot & 31;
        int row = row0 + r;
        float4 v = make_float4(0.f, 0.f, 0.f, 0.f);
        if (row < N) v = __ldg((const float4*)(g_h + (size_t)row * HD) + k4);
        float* p = hsh + r * HS + k4 * 4;
        p[0] = v.x; p[1] = v.y; p[2] = v.z; p[3] = v.w;
    }
    __syncthreads();

    const int tx = tid & 15, ty = tid >> 4;
    const int c0 = tx * 8;
    const int r0 = ty * 4;

    float acc[4][8];
#pragma unroll
    for (int i = 0; i < 4; i++)
#pragma unroll
        for (int j = 0; j < 8; j++) acc[i][j] = 0.0f;

#pragma unroll 8
    for (int k = 0; k < 128; k++) {
        float a0 = hsh[(r0 + 0) * HS + k];
        float a1 = hsh[(r0 + 1) * HS + k];
        float a2 = hsh[(r0 + 2) * HS + k];
        float a3 = hsh[(r0 + 3) * HS + k];
        float4 w0 = *(const float4*)(Wsh + k * HD + c0);
        float4 w1 = *(const float4*)(Wsh + k * HD + c0 + 4);
        acc[0][0] += a0 * w0.x; acc[0][1] += a0 * w0.y; acc[0][2] += a0 * w0.z; acc[0][3] += a0 * w0.w;
        acc[0][4] += a0 * w1.x; acc[0][5] += a0 * w1.y; acc[0][6] += a0 * w1.z; acc[0][7] += a0 * w1.w;
        acc[1][0] += a1 * w0.x; acc[1][1] += a1 * w0.y; acc[1][2] += a1 * w0.z; acc[1][3] += a1 * w0.w;
        acc[1][4] += a1 * w1.x; acc[1][5] += a1 * w1.y; acc[1][6] += a1 * w1.z; acc[1][7] += a1 * w1.w;
        acc[2][0] += a2 * w0.x; acc[2][1] += a2 * w0.y; acc[2][2] += a2 * w0.z; acc[2][3] += a2 * w0.w;
        acc[2][4] += a2 * w1.x; acc[2][5] += a2 * w1.y; acc[2][6] += a2 * w1.z; acc[2][7] += a2 * w1.w;
        acc[3][0] += a3 * w0.x; acc[3][1] += a3 * w0.y; acc[3][2] += a3 * w0.z; acc[3][3] += a3 * w0.w;
        acc[3][4] += a3 * w1.x; acc[3][5] += a3 * w1.y; acc[3][6] += a3 * w1.z; acc[3][7] += a3 * w1.w;
    }

    const float4 z4 = make_float4(0.f, 0.f, 0.f, 0.f);
#pragma unroll
    for (int i = 0; i < 4; i++) {
        int row = row0 + r0 + i;
        if (row >= N) continue;
        float dv = g_dinv[row];
        float4 o0 = make_float4(acc[i][0] * dv, acc[i][1] * dv, acc[i][2] * dv, acc[i][3] * dv);
        float4 o1 = make_float4(acc[i][4] * dv, acc[i][5] * dv, acc[i][6] * dv, acc[i][7] * dv);
        *(float4*)(g_hw + (size_t)row * HD + c0)     = o0;
        *(float4*)(g_hw + (size_t)row * HD + c0 + 4) = o1;
        *(float4*)(g_acc + (size_t)row * HD + c0)     = z4;   // zero accumulator for scatter
        *(float4*)(g_acc + (size_t)row * HD + c0 + 4) = z4;
    }
}

// ---------------- edge scatter: acc[dst] += hw_s[src] (one warp per edge) ----------------
__global__ void scatter_k(const int* __restrict__ src, const int* __restrict__ dst, int E) {
    int w = (blockIdx.x * blockDim.x + threadIdx.x) >> 5;
    int lane = threadIdx.x & 31;
    if (w >= E) return;
    int s = __ldg(src + w);
    int d = __ldg(dst + w);
    float4 v = __ldg((const float4*)(g_hw + (size_t)s * HD) + lane);
    red4(g_acc + (size_t)d * HD + (size_t)lane * 4, v);
}

// ---------------- finalize: h = [BN+ReLU]((acc + hw_s)*dinv + bias) ----------------
__global__ void finalize_k(const float* __restrict__ bias,
                           const float* __restrict__ gamma, const float* __restrict__ beta,
                           const float* __restrict__ mean, const float* __restrict__ var,
                           int N, int bn) {
    int idx = blockIdx.x * blockDim.x + threadIdx.x;   // float4 index
    if (idx >= N * 32) return;
    int n = idx >> 5;
    int c = (idx & 31) * 4;
    float dv = g_dinv[n];
    float4 a = *(const float4*)(g_acc + (size_t)n * HD + c);
    float4 w = *(const float4*)(g_hw + (size_t)n * HD + c);
    float o[4] = { (a.x + w.x), (a.y + w.y), (a.z + w.z), (a.w + w.w) };
#pragma unroll
    for (int j = 0; j < 4; j++) {
        float v = o[j] * dv + __ldg(bias + c + j);
        if (bn) {
            float sc = __ldg(gamma + c + j) * rsqrtf(__ldg(var + c + j) + BN_EPS);
            v = (v - __ldg(mean + c + j)) * sc + __ldg(beta + c + j);
            v = fmaxf(v, 0.0f);
        }
        o[j] = v;
    }
    *(float4*)(g_h + (size_t)n * HD + c) = make_float4(o[0], o[1], o[2], o[3]);
}

// ---------------- pooling ----------------
__global__ void pool_zero_k() {
    int idx = blockIdx.x * blockDim.x + threadIdx.x;
    if (idx < GMAX * HD) g_pool[idx] = 0.0f;
    if (idx < GMAX) g_cnt[idx] = 0.0f;
}
__global__ void pool2_k(const int* __restrict__ batch, int N) {
    int n = (blockIdx.x * blockDim.x + threadIdx.x) >> 5;
    int lane = threadIdx.x & 31;
    if (n >= N) return;
    int b = __ldg(batch + n);
    float4 v = __ldg((const float4*)(g_h + (size_t)n * HD) + lane);
    red4(g_pool + (size_t)b * HD + (size_t)lane * 4, v);
    if (lane == 0) atomicAdd(&g_cnt[b], 1.0f);
}

// ---------------- classifier: out[g] = mean_pool[g] @ Wclf + bclf ----------------
__global__ void clf_k(const float* __restrict__ Wclf, const float* __restrict__ bclf,
                      float* __restrict__ out) {
    int g = blockIdx.x;
    int tid = threadIdx.x;
    __shared__ float sm[HD];
    float inv = 1.0f / fmaxf(g_cnt[g], 1.0f);
    sm[tid] = g_pool[(size_t)g * HD + tid] * inv;
    __syncthreads();
    if (tid < OUTD) {
        float s = __ldg(bclf + tid);
#pragma unroll 16
        for (int k = 0; k < HD; k++) s += sm[k] * __ldg(Wclf + k * OUTD + tid);
        out[(size_t)g * OUTD + tid] = s;
    }
}

// ---------------- launch ----------------
extern "C" void kernel_launch(void* const* d_in, const int* in_sizes, int n_in,
                              void* d_out, int out_size) {
    const int*   x     = (const int*)d_in[0];
    const int*   ei    = (const int*)d_in[1];
    const int*   batch = (const int*)d_in[2];
    const float* emb   = (const float*)d_in[3];
    const float* Ws    = (const float*)d_in[4];
    const float* bs    = (const float*)d_in[5];
    const float* gamma = (const float*)d_in[6];
    const float* beta  = (const float*)d_in[7];
    const float* rmean = (const float*)d_in[8];
    const float* rvar  = (const float*)d_in[9];
    const float* Wclf  = (const float*)d_in[10];
    const float* bclf  = (const float*)d_in[11];
    float* out = (float*)d_out;

    const int N = in_sizes[2];
    const int E = in_sizes[1] / 2;
    const int G = out_size / OUTD;
    const int* src = ei;
    const int* dst = ei + E;

    deg_init_k<<<(N + 255) / 256, 256>>>(N);
    deg_count_k<<<(E + 255) / 256, 256>>>(dst, E);
    dinv_k<<<(N + 255) / 256, 256>>>(N);

    embed_k<<<N, HD>>>(x, emb, N);

    const int SMEM = (HD * HD + 64 * HS) * (int)sizeof(float);
    cudaFuncSetAttribute(gemm_k, cudaFuncAttributeMaxDynamicSharedMemorySize, SMEM);

    for (int l = 0; l < 3; l++) {
        int bl = (l < 2) ? l : 0;  // avoid OOB pointer math for last layer (bn unused)
        gemm_k<<<(N + 63) / 64, 256, SMEM>>>(Ws + (size_t)l * HD * HD, N);
        scatter_k<<<(E + 7) / 8, 256>>>(src, dst, E);
        finalize_k<<<(N * 32 + 255) / 256, 256>>>(bs + (size_t)l * HD,
                                                  gamma + (size_t)bl * HD, beta + (size_t)bl * HD,
                                                  rmean + (size_t)bl * HD, rvar + (size_t)bl * HD,
                                                  N, l < 2 ? 1 : 0);
    }

    pool_zero_k<<<(GMAX * HD + 255) / 256, 256>>>();
    pool2_k<<<(N + 7) / 8, 256>>>(batch, N);
    clf_k<<<G, HD>>>(Wclf, bclf, out);
}

// round 4
// speedup vs baseline: 1.0341x; 1.0341x over previous
#include <cuda_runtime.h>
#include <cstdint>

#define NF 9
#define HD 128
#define VOCAB 128
#define GMAX 1024
#define OUTD 10
#define MAXN 100000
#define BN_EPS 1e-5f

// ---------------- scratch (device globals; no allocs allowed) ----------------
__device__ float g_h[(size_t)MAXN * HD];
__device__ float g_hw[(size_t)MAXN * HD];
__device__ float g_acc[(size_t)MAXN * HD];
__device__ float g_deg[MAXN];
__device__ float g_dinv[MAXN];
__device__ float g_pool[GMAX * HD];
__device__ float g_cnt[GMAX];

// 128-bit vector reduction: 4 f32 adds in one L2 atomic op
__device__ __forceinline__ void red4(float* p, float4 v) {
    asm volatile("red.global.add.v4.f32 [%0], {%1,%2,%3,%4};"
                 :: "l"(p), "f"(v.x), "f"(v.y), "f"(v.z), "f"(v.w) : "memory");
}

// ---------------- degree / dinv ----------------
__global__ void deg_init_k(int N) {
    int n = blockIdx.x * blockDim.x + threadIdx.x;
    if (n < N) g_deg[n] = 1.0f;   // self-loop
}
__global__ void deg_count_k(const int* __restrict__ dst, int E) {
    int e = blockIdx.x * blockDim.x + threadIdx.x;
    if (e < E) atomicAdd(&g_deg[dst[e]], 1.0f);
}
__global__ void dinv_k(int N) {
    int n = blockIdx.x * blockDim.x + threadIdx.x;
    if (n < N) g_dinv[n] = rsqrtf(g_deg[n]);
}

// ---------------- AtomEncoder: h[n][c] = sum_f emb[f][x[n][f]][c] ----------------
__global__ void embed_k(const int* __restrict__ x, const float* __restrict__ emb, int N) {
    int n = blockIdx.x;
    int c = threadIdx.x;
    const int* xr = x + (size_t)n * NF;
    float s = 0.0f;
#pragma unroll
    for (int f = 0; f < NF; f++) {
        int id = __ldg(xr + f);
        s += __ldg(emb + ((size_t)f * VOCAB + id) * HD + c);
    }
    g_h[(size_t)n * HD + c] = s;
}

// ---------------- GEMM: hw_s = (g_h @ W) * dinv[row]; also zeroes g_acc ----------------
#define HS 132   // padded hsh row stride
__global__ __launch_bounds__(256) void gemm_k(const float* __restrict__ W, int N) {
    extern __shared__ float smem[];
    float* Wsh = smem;                 // 128*128
    float* hsh = smem + HD * HD;       // 64*HS
    const int tid = threadIdx.x;
    const int row0 = blockIdx.x * 64;

    // load W (128x128 = 4096 float4)
#pragma unroll
    for (int i = 0; i < 16; i++) {
        int idx = tid + i * 256;
        ((float4*)Wsh)[idx] = __ldg((const float4*)W + idx);
    }
    // load h tile (64x128 -> padded stride)
#pragma unroll
    for (int i = 0; i < 8; i++) {
        int slot = tid + i * 256;          // float4 slot over 64x32
        int r = slot >> 5, k4 = slot & 31;
        int row = row0 + r;
        float4 v = make_float4(0.f, 0.f, 0.f, 0.f);
        if (row < N) v = __ldg((const float4*)(g_h + (size_t)row * HD) + k4);
        float* p = hsh + r * HS + k4 * 4;
        p[0] = v.x; p[1] = v.y; p[2] = v.z; p[3] = v.w;
    }
    __syncthreads();

    const int tx = tid & 15, ty = tid >> 4;
    const int c0 = tx * 8;
    const int r0 = ty * 4;

    float acc[4][8];
#pragma unroll
    for (int i = 0; i < 4; i++)
#pragma unroll
        for (int j = 0; j < 8; j++) acc[i][j] = 0.0f;

#pragma unroll 8
    for (int k = 0; k < 128; k++) {
        float a0 = hsh[(r0 + 0) * HS + k];
        float a1 = hsh[(r0 + 1) * HS + k];
        float a2 = hsh[(r0 + 2) * HS + k];
        float a3 = hsh[(r0 + 3) * HS + k];
        float4 w0 = *(const float4*)(Wsh + k * HD + c0);
        float4 w1 = *(const float4*)(Wsh + k * HD + c0 + 4);
        acc[0][0] += a0 * w0.x; acc[0][1] += a0 * w0.y; acc[0][2] += a0 * w0.z; acc[0][3] += a0 * w0.w;
        acc[0][4] += a0 * w1.x; acc[0][5] += a0 * w1.y; acc[0][6] += a0 * w1.z; acc[0][7] += a0 * w1.w;
        acc[1][0] += a1 * w0.x; acc[1][1] += a1 * w0.y; acc[1][2] += a1 * w0.z; acc[1][3] += a1 * w0.w;
        acc[1][4] += a1 * w1.x; acc[1][5] += a1 * w1.y; acc[1][6] += a1 * w1.z; acc[1][7] += a1 * w1.w;
        acc[2][0] += a2 * w0.x; acc[2][1] += a2 * w0.y; acc[2][2] += a2 * w0.z; acc[2][3] += a2 * w0.w;
        acc[2][4] += a2 * w1.x; acc[2][5] += a2 * w1.y; acc[2][6] += a2 * w1.z; acc[2][7] += a2 * w1.w;
        acc[3][0] += a3 * w0.x; acc[3][1] += a3 * w0.y; acc[3][2] += a3 * w0.z; acc[3][3] += a3 * w0.w;
        acc[3][4] += a3 * w1.x; acc[3][5] += a3 * w1.y; acc[3][6] += a3 * w1.z; acc[3][7] += a3 * w1.w;
    }

    const float4 z4 = make_float4(0.f, 0.f, 0.f, 0.f);
#pragma unroll
    for (int i = 0; i < 4; i++) {
        int row = row0 + r0 + i;
        if (row >= N) continue;
        float dv = g_dinv[row];
        float4 o0 = make_float4(acc[i][0] * dv, acc[i][1] * dv, acc[i][2] * dv, acc[i][3] * dv);
        float4 o1 = make_float4(acc[i][4] * dv, acc[i][5] * dv, acc[i][6] * dv, acc[i][7] * dv);
        *(float4*)(g_hw + (size_t)row * HD + c0)     = o0;
        *(float4*)(g_hw + (size_t)row * HD + c0 + 4) = o1;
        *(float4*)(g_acc + (size_t)row * HD + c0)     = z4;   // zero accumulator for scatter
        *(float4*)(g_acc + (size_t)row * HD + c0 + 4) = z4;
    }
}

// ---------------- edge scatter: acc[dst] += hw_s[src] (one warp per edge) ----------------
__global__ void scatter_k(const int* __restrict__ src, const int* __restrict__ dst, int E) {
    int w = (blockIdx.x * blockDim.x + threadIdx.x) >> 5;
    int lane = threadIdx.x & 31;
    if (w >= E) return;
    int s = __ldg(src + w);
    int d = __ldg(dst + w);
    float4 v = __ldg((const float4*)(g_hw + (size_t)s * HD) + lane);
    red4(g_acc + (size_t)d * HD + (size_t)lane * 4, v);
}

// ---------------- finalize: h = [BN+ReLU]((acc + hw_s)*dinv + bias) ----------------
__global__ void finalize_k(const float* __restrict__ bias,
                           const float* __restrict__ gamma, const float* __restrict__ beta,
                           const float* __restrict__ mean, const float* __restrict__ var,
                           int N, int bn) {
    int idx = blockIdx.x * blockDim.x + threadIdx.x;   // float4 index
    if (idx >= N * 32) return;
    int n = idx >> 5;
    int c = (idx & 31) * 4;
    float dv = g_dinv[n];
    float4 a = *(const float4*)(g_acc + (size_t)n * HD + c);
    float4 w = *(const float4*)(g_hw + (size_t)n * HD + c);
    float o[4] = { (a.x + w.x), (a.y + w.y), (a.z + w.z), (a.w + w.w) };
#pragma unroll
    for (int j = 0; j < 4; j++) {
        float v = o[j] * dv + __ldg(bias + c + j);
        if (bn) {
            float sc = __ldg(gamma + c + j) * rsqrtf(__ldg(var + c + j) + BN_EPS);
            v = (v - __ldg(mean + c + j)) * sc + __ldg(beta + c + j);
            v = fmaxf(v, 0.0f);
        }
        o[j] = v;
    }
    *(float4*)(g_h + (size_t)n * HD + c) = make_float4(o[0], o[1], o[2], o[3]);
}

// ---------------- pooling ----------------
__global__ void pool_zero_k() {
    int idx = blockIdx.x * blockDim.x + threadIdx.x;
    if (idx < GMAX * HD) g_pool[idx] = 0.0f;
    if (idx < GMAX) g_cnt[idx] = 0.0f;
}
__global__ void pool2_k(const int* __restrict__ batch, int N) {
    int n = (blockIdx.x * blockDim.x + threadIdx.x) >> 5;
    int lane = threadIdx.x & 31;
    if (n >= N) return;
    int b = __ldg(batch + n);
    float4 v = __ldg((const float4*)(g_h + (size_t)n * HD) + lane);
    red4(g_pool + (size_t)b * HD + (size_t)lane * 4, v);
    if (lane == 0) atomicAdd(&g_cnt[b], 1.0f);
}

// ---------------- classifier: out[g] = mean_pool[g] @ Wclf + bclf ----------------
__global__ void clf_k(const float* __restrict__ Wclf, const float* __restrict__ bclf,
                      float* __restrict__ out) {
    int g = blockIdx.x;
    int tid = threadIdx.x;
    __shared__ float sm[HD];
    float inv = 1.0f / fmaxf(g_cnt[g], 1.0f);
    sm[tid] = g_pool[(size_t)g * HD + tid] * inv;
    __syncthreads();
    if (tid < OUTD) {
        float s = __ldg(bclf + tid);
#pragma unroll 16
        for (int k = 0; k < HD; k++) s += sm[k] * __ldg(Wclf + k * OUTD + tid);
        out[(size_t)g * OUTD + tid] = s;
    }
}

// ---------------- launch ----------------
extern "C" void kernel_launch(void* const* d_in, const int* in_sizes, int n_in,
                              void* d_out, int out_size) {
    const int*   x     = (const int*)d_in[0];
    const int*   ei    = (const int*)d_in[1];
    const int*   batch = (const int*)d_in[2];
    const float* emb   = (const float*)d_in[3];
    const float* Ws    = (const float*)d_in[4];
    const float* bs    = (const float*)d_in[5];
    const float* gamma = (const float*)d_in[6];
    const float* beta  = (const float*)d_in[7];
    const float* rmean = (const float*)d_in[8];
    const float* rvar  = (const float*)d_in[9];
    const float* Wclf  = (const float*)d_in[10];
    const float* bclf  = (const float*)d_in[11];
    float* out = (float*)d_out;

    const int N = in_sizes[2];
    const int E = in_sizes[1] / 2;
    const int G = out_size / OUTD;
    const int* src = ei;
    const int* dst = ei + E;

    deg_init_k<<<(N + 255) / 256, 256>>>(N);
    deg_count_k<<<(E + 255) / 256, 256>>>(dst, E);
    dinv_k<<<(N + 255) / 256, 256>>>(N);

    embed_k<<<N, HD>>>(x, emb, N);

    const int SMEM = (HD * HD + 64 * HS) * (int)sizeof(float);
    cudaFuncSetAttribute(gemm_k, cudaFuncAttributeMaxDynamicSharedMemorySize, SMEM);

    for (int l = 0; l < 3; l++) {
        int bl = (l < 2) ? l : 0;  // avoid OOB pointer math for last layer (bn unused)
        gemm_k<<<(N + 63) / 64, 256, SMEM>>>(Ws + (size_t)l * HD * HD, N);
        scatter_k<<<(E + 7) / 8, 256>>>(src, dst, E);
        finalize_k<<<(N * 32 + 255) / 256, 256>>>(bs + (size_t)l * HD,
                                                  gamma + (size_t)bl * HD, beta + (size_t)bl * HD,
                                                  rmean + (size_t)bl * HD, rvar + (size_t)bl * HD,
                                                  N, l < 2 ? 1 : 0);
    }

    pool_zero_k<<<(GMAX * HD + 255) / 256, 256>>>();
    pool2_k<<<(N + 7) / 8, 256>>>(batch, N);
    clf_k<<<G, HD>>>(Wclf, bclf, out);
}

// round 5
// speedup vs baseline: 2.1378x; 2.0673x over previous
#include <cuda_runtime.h>
#include <cstdint>

#define NF 9
#define HD 128
#define VOCAB 128
#define GMAX 1024
#define OUTD 10
#define MAXN 100000
#define MAXE 1700000
#define BN_EPS 1e-5f

// ---------------- scratch (device globals; no allocs allowed) ----------------
__device__ float g_h[(size_t)MAXN * HD];
__device__ float g_hw[(size_t)MAXN * HD];
__device__ float g_dinv[MAXN];
__device__ int   g_cnt_i[MAXN];
__device__ int   g_start[MAXN + 1];
__device__ int   g_cur[MAXN];
__device__ int   g_csrc[MAXE];
__device__ int   g_bsum[512];
__device__ int   g_boff[512];
__device__ float g_embw[(size_t)NF * VOCAB * HD];
__device__ float g_pool[GMAX * HD];
__device__ float g_cnt[GMAX];

// 128-bit vector reduction (pooling only)
__device__ __forceinline__ void red4(float* p, float4 v) {
    asm volatile("red.global.add.v4.f32 [%0], {%1,%2,%3,%4};"
                 :: "l"(p), "f"(v.x), "f"(v.y), "f"(v.z), "f"(v.w) : "memory");
}

// ---------------- degree counting ----------------
__global__ void cnt_zero_k(int N) {
    int n = blockIdx.x * blockDim.x + threadIdx.x;
    if (n < N) g_cnt_i[n] = 0;
}
__global__ void cnt_k(const int* __restrict__ dst, int E) {
    int e = blockIdx.x * blockDim.x + threadIdx.x;
    if (e < E) atomicAdd(&g_cnt_i[dst[e]], 1);
}
__global__ void dinv_k(int N) {
    int n = blockIdx.x * blockDim.x + threadIdx.x;
    if (n < N) g_dinv[n] = rsqrtf(1.0f + (float)g_cnt_i[n]);
}

// ---------------- CSR build: 2-level exclusive scan + cursor fill ----------------
__global__ void bsum_k(int N) {
    __shared__ int sh[256];
    int n = blockIdx.x * 256 + threadIdx.x;
    sh[threadIdx.x] = (n < N) ? g_cnt_i[n] : 0;
    __syncthreads();
#pragma unroll
    for (int s = 128; s > 0; s >>= 1) {
        if (threadIdx.x < s) sh[threadIdx.x] += sh[threadIdx.x + s];
        __syncthreads();
    }
    if (threadIdx.x == 0) g_bsum[blockIdx.x] = sh[0];
}
__global__ void scanb_k(int nb) {  // single block, 512 threads
    __shared__ int a[512], b[512];
    int t = threadIdx.x;
    int v = (t < nb) ? g_bsum[t] : 0;
    a[t] = v;
    __syncthreads();
    int* in = a; int* out = b;
#pragma unroll
    for (int off = 1; off < 512; off <<= 1) {
        int x = in[t];
        if (t >= off) x += in[t - off];
        out[t] = x;
        __syncthreads();
        int* tmp = in; in = out; out = tmp;
    }
    if (t < nb) g_boff[t] = in[t] - v;   // exclusive
}
__global__ void scanlocal_k(int N) {
    __shared__ int a[256], b[256];
    int t = threadIdx.x;
    int n = blockIdx.x * 256 + t;
    int v = (n < N) ? g_cnt_i[n] : 0;
    a[t] = v;
    __syncthreads();
    int* in = a; int* out = b;
#pragma unroll
    for (int off = 1; off < 256; off <<= 1) {
        int x = in[t];
        if (t >= off) x += in[t - off];
        out[t] = x;
        __syncthreads();
        int* tmp = in; in = out; out = tmp;
    }
    int excl = in[t] - v;
    if (n < N) {
        int s = excl + g_boff[blockIdx.x];
        g_start[n] = s;
        g_cur[n] = s;
        if (n == N - 1) g_start[N] = s + v;
    }
}
__global__ void fill_k(const int* __restrict__ src, const int* __restrict__ dst, int E) {
    int e = blockIdx.x * blockDim.x + threadIdx.x;
    if (e < E) {
        int pos = atomicAdd(&g_cur[dst[e]], 1);
        g_csrc[pos] = src[e];
    }
}

// ---------------- embW[f][v] = emb[f][v] @ W0  (tiny GEMM, 1152 rows) ----------------
__global__ void embw_k(const float* __restrict__ emb, const float* __restrict__ W) {
    __shared__ float row[HD];
    int r = blockIdx.x;
    int c = threadIdx.x;
    row[c] = __ldg(emb + (size_t)r * HD + c);
    __syncthreads();
    float s = 0.0f;
#pragma unroll 8
    for (int k = 0; k < HD; k++) s += row[k] * __ldg(W + k * HD + c);
    g_embw[(size_t)r * HD + c] = s;
}

// ---------------- fused AtomEncoder + layer-0 projection: hw0 = (Σ_f embW[f][x_f]) * dinv ----------------
__global__ void embhw_k(const int* __restrict__ x, int N) {
    int w = (blockIdx.x * blockDim.x + threadIdx.x) >> 5;
    int lane = threadIdx.x & 31;
    if (w >= N) return;
    const int* xr = x + (size_t)w * NF;
    float4 acc = make_float4(0.f, 0.f, 0.f, 0.f);
#pragma unroll
    for (int f = 0; f < NF; f++) {
        int id = __ldg(xr + f);
        float4 v = __ldg((const float4*)(g_embw + (size_t)(f * VOCAB + id) * HD) + lane);
        acc.x += v.x; acc.y += v.y; acc.z += v.z; acc.w += v.w;
    }
    float dv = g_dinv[w];
    acc.x *= dv; acc.y *= dv; acc.z *= dv; acc.w *= dv;
    *((float4*)(g_hw + (size_t)w * HD) + lane) = acc;
}

// ---------------- GEMM: hw = (g_h @ W) * dinv[row] ----------------
#define HS 132
__global__ __launch_bounds__(256) void gemm_k(const float* __restrict__ W, int N) {
    extern __shared__ float smem[];
    float* Wsh = smem;                 // 128*128
    float* hsh = smem + HD * HD;       // 64*HS
    const int tid = threadIdx.x;
    const int row0 = blockIdx.x * 64;

#pragma unroll
    for (int i = 0; i < 16; i++) {
        int idx = tid + i * 256;
        ((float4*)Wsh)[idx] = __ldg((const float4*)W + idx);
    }
#pragma unroll
    for (int i = 0; i < 8; i++) {
        int slot = tid + i * 256;
        int r = slot >> 5, k4 = slot & 31;
        int row = row0 + r;
        float4 v = make_float4(0.f, 0.f, 0.f, 0.f);
        if (row < N) v = __ldg((const float4*)(g_h + (size_t)row * HD) + k4);
        float* p = hsh + r * HS + k4 * 4;
        p[0] = v.x; p[1] = v.y; p[2] = v.z; p[3] = v.w;
    }
    __syncthreads();

    const int tx = tid & 15, ty = tid >> 4;
    const int c0 = tx * 8;
    const int r0 = ty * 4;

    float acc[4][8];
#pragma unroll
    for (int i = 0; i < 4; i++)
#pragma unroll
        for (int j = 0; j < 8; j++) acc[i][j] = 0.0f;

#pragma unroll 8
    for (int k = 0; k < 128; k++) {
        float a0 = hsh[(r0 + 0) * HS + k];
        float a1 = hsh[(r0 + 1) * HS + k];
        float a2 = hsh[(r0 + 2) * HS + k];
        float a3 = hsh[(r0 + 3) * HS + k];
        float4 w0 = *(const float4*)(Wsh + k * HD + c0);
        float4 w1 = *(const float4*)(Wsh + k * HD + c0 + 4);
        acc[0][0] += a0 * w0.x; acc[0][1] += a0 * w0.y; acc[0][2] += a0 * w0.z; acc[0][3] += a0 * w0.w;
        acc[0][4] += a0 * w1.x; acc[0][5] += a0 * w1.y; acc[0][6] += a0 * w1.z; acc[0][7] += a0 * w1.w;
        acc[1][0] += a1 * w0.x; acc[1][1] += a1 * w0.y; acc[1][2] += a1 * w0.z; acc[1][3] += a1 * w0.w;
        acc[1][4] += a1 * w1.x; acc[1][5] += a1 * w1.y; acc[1][6] += a1 * w1.z; acc[1][7] += a1 * w1.w;
        acc[2][0] += a2 * w0.x; acc[2][1] += a2 * w0.y; acc[2][2] += a2 * w0.z; acc[2][3] += a2 * w0.w;
        acc[2][4] += a2 * w1.x; acc[2][5] += a2 * w1.y; acc[2][6] += a2 * w1.z; acc[2][7] += a2 * w1.w;
        acc[3][0] += a3 * w0.x; acc[3][1] += a3 * w0.y; acc[3][2] += a3 * w0.z; acc[3][3] += a3 * w0.w;
        acc[3][4] += a3 * w1.x; acc[3][5] += a3 * w1.y; acc[3][6] += a3 * w1.z; acc[3][7] += a3 * w1.w;
    }

#pragma unroll
    for (int i = 0; i < 4; i++) {
        int row = row0 + r0 + i;
        if (row >= N) continue;
        float dv = g_dinv[row];
        float4 o0 = make_float4(acc[i][0] * dv, acc[i][1] * dv, acc[i][2] * dv, acc[i][3] * dv);
        float4 o1 = make_float4(acc[i][4] * dv, acc[i][5] * dv, acc[i][6] * dv, acc[i][7] * dv);
        *(float4*)(g_hw + (size_t)row * HD + c0)     = o0;
        *(float4*)(g_hw + (size_t)row * HD + c0 + 4) = o1;
    }
}

// ---------------- fused aggregate + finalize (warp per node, CSR gather, no atomics) ----------------
__global__ void agg_k(const float* __restrict__ bias,
                      const float* __restrict__ gamma, const float* __restrict__ beta,
                      const float* __restrict__ mean, const float* __restrict__ var,
                      int N, int bn) {
    int w = (blockIdx.x * blockDim.x + threadIdx.x) >> 5;
    int lane = threadIdx.x & 31;
    if (w >= N) return;
    int s0 = __ldg(g_start + w);
    int s1 = __ldg(g_start + w + 1);
    // self-loop term
    float4 acc = __ldg((const float4*)(g_hw + (size_t)w * HD) + lane);
#pragma unroll 4
    for (int e = s0; e < s1; e++) {
        int s = __ldg(g_csrc + e);
        float4 v = __ldg((const float4*)(g_hw + (size_t)s * HD) + lane);
        acc.x += v.x; acc.y += v.y; acc.z += v.z; acc.w += v.w;
    }
    float dv = g_dinv[w];
    int c = lane * 4;
    float o[4] = { acc.x * dv + __ldg(bias + c + 0),
                   acc.y * dv + __ldg(bias + c + 1),
                   acc.z * dv + __ldg(bias + c + 2),
                   acc.w * dv + __ldg(bias + c + 3) };
    if (bn) {
#pragma unroll
        for (int j = 0; j < 4; j++) {
            float sc = __ldg(gamma + c + j) * rsqrtf(__ldg(var + c + j) + BN_EPS);
            float v = (o[j] - __ldg(mean + c + j)) * sc + __ldg(beta + c + j);
            o[j] = fmaxf(v, 0.0f);
        }
    }
    *((float4*)(g_h + (size_t)w * HD) + lane) = make_float4(o[0], o[1], o[2], o[3]);
}

// ---------------- pooling ----------------
__global__ void pool_zero_k() {
    int idx = blockIdx.x * blockDim.x + threadIdx.x;
    if (idx < GMAX * HD) g_pool[idx] = 0.0f;
    if (idx < GMAX) g_cnt[idx] = 0.0f;
}
__global__ void pool2_k(const int* __restrict__ batch, int N) {
    int n = (blockIdx.x * blockDim.x + threadIdx.x) >> 5;
    int lane = threadIdx.x & 31;
    if (n >= N) return;
    int b = __ldg(batch + n);
    float4 v = __ldg((const float4*)(g_h + (size_t)n * HD) + lane);
    red4(g_pool + (size_t)b * HD + (size_t)lane * 4, v);
    if (lane == 0) atomicAdd(&g_cnt[b], 1.0f);
}

// ---------------- classifier ----------------
__global__ void clf_k(const float* __restrict__ Wclf, const float* __restrict__ bclf,
                      float* __restrict__ out) {
    int g = blockIdx.x;
    int tid = threadIdx.x;
    __shared__ float sm[HD];
    float inv = 1.0f / fmaxf(g_cnt[g], 1.0f);
    sm[tid] = g_pool[(size_t)g * HD + tid] * inv;
    __syncthreads();
    if (tid < OUTD) {
        float s = __ldg(bclf + tid);
#pragma unroll 16
        for (int k = 0; k < HD; k++) s += sm[k] * __ldg(Wclf + k * OUTD + tid);
        out[(size_t)g * OUTD + tid] = s;
    }
}

// ---------------- launch ----------------
extern "C" void kernel_launch(void* const* d_in, const int* in_sizes, int n_in,
                              void* d_out, int out_size) {
    const int*   x     = (const int*)d_in[0];
    const int*   ei    = (const int*)d_in[1];
    const int*   batch = (const int*)d_in[2];
    const float* emb   = (const float*)d_in[3];
    const float* Ws    = (const float*)d_in[4];
    const float* bs    = (const float*)d_in[5];
    const float* gamma = (const float*)d_in[6];
    const float* beta  = (const float*)d_in[7];
    const float* rmean = (const float*)d_in[8];
    const float* rvar  = (const float*)d_in[9];
    const float* Wclf  = (const float*)d_in[10];
    const float* bclf  = (const float*)d_in[11];
    float* out = (float*)d_out;

    const int N = in_sizes[2];
    const int E = in_sizes[1] / 2;
    const int G = out_size / OUTD;
    const int* src = ei;
    const int* dst = ei + E;
    const int nb = (N + 255) / 256;

    // degree + CSR build
    cnt_zero_k<<<nb, 256>>>(N);
    cnt_k<<<(E + 255) / 256, 256>>>(dst, E);
    dinv_k<<<nb, 256>>>(N);
    bsum_k<<<nb, 256>>>(N);
    scanb_k<<<1, 512>>>(nb);
    scanlocal_k<<<nb, 256>>>(N);
    fill_k<<<(E + 255) / 256, 256>>>(src, dst, E);

    // fused embedding + layer-0 projection
    embw_k<<<NF * VOCAB, HD>>>(emb, Ws);
    embhw_k<<<(N * 32 + 255) / 256, 256>>>(x, N);

    const int SMEM = (HD * HD + 64 * HS) * (int)sizeof(float);
    cudaFuncSetAttribute(gemm_k, cudaFuncAttributeMaxDynamicSharedMemorySize, SMEM);

    for (int l = 0; l < 3; l++) {
        int bl = (l < 2) ? l : 0;
        agg_k<<<(N * 32 + 255) / 256, 256>>>(bs + (size_t)l * HD,
                                             gamma + (size_t)bl * HD, beta + (size_t)bl * HD,
                                             rmean + (size_t)bl * HD, rvar + (size_t)bl * HD,
                                             N, l < 2 ? 1 : 0);
        if (l < 2)
            gemm_k<<<(N + 63) / 64, 256, SMEM>>>(Ws + (size_t)(l + 1) * HD * HD, N);
    }

    pool_zero_k<<<(GMAX * HD + 255) / 256, 256>>>();
    pool2_k<<<(N + 7) / 8, 256>>>(batch, N);
    clf_k<<<G, HD>>>(Wclf, bclf, out);
}